// round 11
// baseline (speedup 1.0000x reference)
#include <cuda_runtime.h>
#include <cuda_fp16.h>
#include <cstdint>

#define B_    16
#define T_    8
#define KBANK 64
#define COUT  128
#define CIN   128
#define HH    64
#define WW    64
#define HP    68
#define WP    68
#define PPW   (COUT * CIN * 25)        // 409600

// ---------------- device scratch (allocation-free) ----------------
__device__ float g_lp[(size_t)B_ * PPW];                      // fp32 [b][o][c][tap]
// A in fragment-major layout: [b][tap][oblock(8)][kblock(8)][lane(32)][4 words]
__device__ uint4 g_Af[(size_t)B_ * 25 * 8 * 8 * 32];
__device__ unsigned g_xph[(size_t)B_ * (CIN / 2) * HP * WP];  // half2 [b][cp][hp][wp]

// ---------------- PTX helpers ----------------
__device__ __forceinline__ uint32_t smem_u32(const void* p) {
    uint32_t a;
    asm("{ .reg .u64 t; cvta.to.shared.u64 t, %1; cvt.u32.u64 %0, t; }" : "=r"(a) : "l"(p));
    return a;
}
#define CP16(smem, gmem) \
    asm volatile("cp.async.cg.shared.global [%0], [%1], 16;" :: "r"(smem), "l"(gmem))
#define CP_COMMIT() asm volatile("cp.async.commit_group;" ::: "memory")
#define CP_WAIT0()  asm volatile("cp.async.wait_group 0;" ::: "memory")

#define MMA16816(c, a, b0v, b1v) \
    asm volatile("mma.sync.aligned.m16n8k16.row.col.f32.f16.f16.f32 " \
        "{%0,%1,%2,%3}, {%4,%5,%6,%7}, {%8,%9}, {%0,%1,%2,%3};" \
        : "+f"((c)[0]), "+f"((c)[1]), "+f"((c)[2]), "+f"((c)[3]) \
        : "r"((a).x), "r"((a).y), "r"((a).z), "r"((a).w), "r"(b0v), "r"(b1v))

// ---------------------------------------------------------------------------
// K1: fused coeff + lp (float2 streaming):
//   g_lp[b][p] = sum_k (mean_t tf[b,t,k]) * W[k][p], 2 columns per thread
// ---------------------------------------------------------------------------
__global__ __launch_bounds__(256) void lp_kernel(const float* __restrict__ W,
                                                 const float* __restrict__ tf) {
    __shared__ float sc[B_ * KBANK];
    int tid = threadIdx.x;
    for (int i = tid; i < B_ * KBANK; i += 256) {
        int b = i >> 6, k = i & 63;
        float s = 0.f;
#pragma unroll
        for (int t = 0; t < T_; t++) s += tf[(b * T_ + t) * KBANK + k];
        sc[i] = s * (1.0f / (float)T_);
    }
    __syncthreads();
    size_t p2 = (size_t)blockIdx.x * 512 + tid * 2;
    float ax[B_], ay[B_];
#pragma unroll
    for (int b = 0; b < B_; b++) { ax[b] = 0.f; ay[b] = 0.f; }
    for (int k = 0; k < KBANK; k++) {
        float2 wv = *(const float2*)&W[(size_t)k * PPW + p2];
#pragma unroll
        for (int b = 0; b < B_; b++) {
            float c = sc[b * KBANK + k];
            ax[b] = fmaf(c, wv.x, ax[b]);
            ay[b] = fmaf(c, wv.y, ay[b]);
        }
    }
#pragma unroll
    for (int b = 0; b < B_; b++)
        *(float2*)&g_lp[(size_t)b * PPW + p2] = make_float2(ax[b], ay[b]);
}

// ---------------------------------------------------------------------------
// K2: pack A fragments — smem-transposed, coalesced both sides.
// grid (oq=8, b=16), 256 thr. Per kb-chunk (16 c's): stage [16 o][16 c][25 tap]
// slab (coalesced 400-float row reads), then emit 32-lane uint4 frag rows.
// Frag word mapping (must match conv): lane=(g*4+t), o0=oq*16+g, c0=2(kb*8+t):
//   x=(o0,c0|c0+1) y=(o0+8,·) z=(o0,c0+8|c0+9) w=(o0+8,·)
// ---------------------------------------------------------------------------
#define APITCH 404   // 16*25 + 4 pad (floats); o-row stride in smem
__global__ __launch_bounds__(256) void apack_kernel() {
    __shared__ float s[16 * APITCH];   // 25.9 KB
    const int oq = blockIdx.x, b = blockIdx.y;
    const int tid = threadIdx.x;
    const float* lpb = g_lp + (size_t)b * PPW + (size_t)(oq * 16) * CIN * 25;
    uint4* dstb = g_Af + (size_t)b * 25 * 2048 + oq * 256;

    for (int kb = 0; kb < 8; kb++) {
        // load slab: rows o_l 0..15, floats [kb*16*25 .. +400) of each o-row
        for (int idx = tid; idx < 16 * 400; idx += 256) {
            int o_l = idx / 400, r = idx - o_l * 400;
            s[o_l * APITCH + r] = lpb[(size_t)o_l * CIN * 25 + kb * 400 + r];
        }
        __syncthreads();
        // emit: 25 taps x 32 lanes
        for (int idx = tid; idx < 800; idx += 256) {
            int lane = idx & 31, tap = idx >> 5;
            int g = lane >> 2, t = lane & 3;
            const float* r0 = s + g * APITCH + (2 * t) * 25 + tap;        // o=g
            const float* r1 = r0 + 8 * APITCH;                            // o=g+8
            __half2 hx = __floats2half2_rn(r0[0],        r0[25]);
            __half2 hy = __floats2half2_rn(r1[0],        r1[25]);
            __half2 hz = __floats2half2_rn(r0[8 * 25],   r0[9 * 25]);
            __half2 hw = __floats2half2_rn(r1[8 * 25],   r1[9 * 25]);
            uint4 v;
            v.x = *(unsigned*)&hx; v.y = *(unsigned*)&hy;
            v.z = *(unsigned*)&hz; v.w = *(unsigned*)&hw;
            dstb[(size_t)tap * 2048 + kb * 32 + lane] = v;
        }
        __syncthreads();
    }
}

// ---------------------------------------------------------------------------
// K3: g_xph[b][cp][hp][wp] = half2(x[b][2cp][h][w], x[b][2cp+1][h][w]), pad 0
// ---------------------------------------------------------------------------
__global__ __launch_bounds__(256) void xpad_kernel(const float* __restrict__ x) {
    const int cp = blockIdx.x, b = blockIdx.y;
    const float* x0 = x + ((size_t)(b * CIN + 2 * cp) * HH) * WW;
    const float* x1 = x0 + HH * WW;
    unsigned* dst = g_xph + ((size_t)(b * 64 + cp) * HP) * WP;
    for (int i = threadIdx.x; i < HP * WP; i += 256) {
        int hp = i / WP, wp = i - hp * WP;
        int h = hp - 2, w = wp - 2;
        float v0 = 0.f, v1 = 0.f;
        if ((unsigned)h < HH && (unsigned)w < WW) {
            v0 = x0[h * WW + w];
            v1 = x1[h * WW + w];
        }
        __half2 hh = __floats2half2_rn(v0, v1);
        dst[i] = *(unsigned*)&hh;
    }
}

// ---------------------------------------------------------------------------
// K4: conv (UNCHANGED from R10 best): 25 tap-GEMMs, mma m16n8k16 fp16/fp32.
// CTA = (b, 1 row): D[128 cout, 64 px]; 8 warps = 4M x 2N, 32x32 warp tile.
// A via coalesced LDG.128 fragments (L1-resident across co-CTAs); B halo in
// smem double-buffered; barriers only at 4 chunk boundaries. 3 CTAs/SM.
// ---------------------------------------------------------------------------
#define BP   344
#define BBUF (16 * BP)
#define SMW  (2 * BBUF)                // 44032 B

__device__ __forceinline__ void stage_b(uint32_t sb, const unsigned* Xbase,
                                        int cc, int h0) {
    const uint32_t dbase = sb + (uint32_t)((cc & 1) * BBUF) * 4;
    for (int idx = threadIdx.x; idx < 1360; idx += 256) {
        int cp = idx / 85, rem = idx - cp * 85;
        int r = rem / 17, f = rem - r * 17;
        const unsigned* src = Xbase + (size_t)(cc * 16 + cp) * HP * WP
                                    + (h0 + r) * WP + f * 4;
        CP16(dbase + (uint32_t)(cp * BP + r * WP + f * 4) * 4, src);
    }
}

__global__ __launch_bounds__(256, 3) void conv_kernel(float* __restrict__ out) {
    extern __shared__ uint32_t sm[];
    const uint32_t sb = smem_u32(sm);
    const int tid = threadIdx.x;
    const int lane = tid & 31;
    const int wid = tid >> 5;
    const int g = lane >> 2, t = lane & 3;
    const int wm = wid & 3;
    const int wn = wid >> 2;
    const int w0 = wn * 32;
    const int b = blockIdx.y, h0 = blockIdx.x;

    const uint4* __restrict__ Aw = g_Af + ((size_t)b * 25 + 0) * 2048
                                 + (size_t)(wm * 2) * 256 + lane;
    const unsigned* Xbase = g_xph + (size_t)b * 64 * HP * WP;

    float acc[2][4][4];
#pragma unroll
    for (int mt = 0; mt < 2; mt++)
#pragma unroll
        for (int nt = 0; nt < 4; nt++)
#pragma unroll
            for (int q = 0; q < 4; q++) acc[mt][nt][q] = 0.f;

    stage_b(sb, Xbase, 0, h0);
    CP_COMMIT();

#pragma unroll 1
    for (int cc = 0; cc < 4; cc++) {
        CP_WAIT0();
        __syncthreads();
        const uint32_t* sB = sm + (cc & 1) * BBUF;

#pragma unroll 5
        for (int tap = 0; tap < 25; tap++) {
            if (tap == 12 && cc < 3) { stage_b(sb, Xbase, cc + 1, h0); CP_COMMIT(); }
            const int di = tap / 5, dj = tap % 5;
            const uint4* ap = Aw + (size_t)tap * 2048 + cc * 64;
            uint4 a00 = ap[0];
            uint4 a01 = ap[32];
            uint4 a10 = ap[256];
            uint4 a11 = ap[256 + 32];
            const int pixbase = di * WP + dj + w0 + g;
#pragma unroll
            for (int kk = 0; kk < 2; kk++) {
                const uint32_t* bp0 = sB + (kk * 8 + t) * BP + pixbase;
                const uint32_t* bp1 = bp0 + 4 * BP;
                uint4 a0 = kk ? a01 : a00;
                uint4 a1 = kk ? a11 : a10;
#pragma unroll
                for (int nt = 0; nt < 4; nt++) {
                    uint32_t b0 = bp0[nt * 8], b1 = bp1[nt * 8];
                    MMA16816(acc[0][nt], a0, b0, b1);
                    MMA16816(acc[1][nt], a1, b0, b1);
                }
            }
        }
    }

    // ---- epilogue ----
#pragma unroll
    for (int mt = 0; mt < 2; mt++) {
#pragma unroll
        for (int rr = 0; rr < 2; rr++) {
            int cout = wm * 32 + mt * 16 + g + rr * 8;
            float* op = out + (((size_t)b * COUT + cout) * HH + h0) * WW + w0;
#pragma unroll
            for (int nt = 0; nt < 4; nt++) {
                float2 v = make_float2(acc[mt][nt][rr * 2], acc[mt][nt][rr * 2 + 1]);
                *(float2*)(op + nt * 8 + 2 * t) = v;
            }
        }
    }
}

// ---------------------------------------------------------------------------
extern "C" void kernel_launch(void* const* d_in, const int* in_sizes, int n_in,
                              void* d_out, int out_size) {
    (void)in_sizes; (void)n_in; (void)out_size;
    const float* x  = (const float*)d_in[0];   // (16,128,64,64)
    const float* tf = (const float*)d_in[1];   // (16,8,64)
    const float* W  = (const float*)d_in[2];   // (64,128,128,5,5)
    float* out = (float*)d_out;                // (16,128,64,64)

    cudaFuncSetAttribute(conv_kernel, cudaFuncAttributeMaxDynamicSharedMemorySize,
                         SMW * 4);

    lp_kernel<<<PPW / 512, 256>>>(W, tf);
    apack_kernel<<<dim3(8, B_), 256>>>();
    xpad_kernel<<<dim3(64, B_), 256>>>(x);
    conv_kernel<<<dim3(HH, B_), 256, SMW * 4>>>(out);
}

// round 12
// speedup vs baseline: 1.2109x; 1.2109x over previous
#include <cuda_runtime.h>
#include <cuda_fp16.h>
#include <cstdint>

#define B_    16
#define T_    8
#define KBANK 64
#define COUT  128
#define CIN   128
#define HH    64
#define WW    64
#define HP    68
#define WP    68
#define PPW   (COUT * CIN * 25)        // 409600

// ---------------- device scratch (allocation-free) ----------------
__device__ float g_lp[(size_t)B_ * PPW];                      // fp32 [b][o][c][tap]
// A fragment-major: [b][tap][oblock(8)][kblock(8)][lane(32)] uint4
__device__ uint4 g_Af[(size_t)B_ * 25 * 8 * 8 * 32];
__device__ unsigned g_xph[(size_t)B_ * (CIN / 2) * HP * WP];  // half2 [b][cp][hp][wp]

// ---------------- PTX helpers ----------------
__device__ __forceinline__ uint32_t smem_u32(const void* p) {
    uint32_t a;
    asm("{ .reg .u64 t; cvta.to.shared.u64 t, %1; cvt.u32.u64 %0, t; }" : "=r"(a) : "l"(p));
    return a;
}
#define CP16(smem, gmem) \
    asm volatile("cp.async.cg.shared.global [%0], [%1], 16;" :: "r"(smem), "l"(gmem))
#define CP_COMMIT() asm volatile("cp.async.commit_group;" ::: "memory")
#define CP_WAIT0()  asm volatile("cp.async.wait_group 0;" ::: "memory")

#define MMA16816(c, a, b0v, b1v) \
    asm volatile("mma.sync.aligned.m16n8k16.row.col.f32.f16.f16.f32 " \
        "{%0,%1,%2,%3}, {%4,%5,%6,%7}, {%8,%9}, {%0,%1,%2,%3};" \
        : "+f"((c)[0]), "+f"((c)[1]), "+f"((c)[2]), "+f"((c)[3]) \
        : "r"((a).x), "r"((a).y), "r"((a).z), "r"((a).w), "r"(b0v), "r"(b1v))

// ---------------------------------------------------------------------------
// K1: fused coeff + lp (R10 known-good scalar version)
// ---------------------------------------------------------------------------
__global__ __launch_bounds__(256) void lp_kernel(const float* __restrict__ W,
                                                 const float* __restrict__ tf) {
    __shared__ float sc[B_ * KBANK];
    int tid = threadIdx.x;
    for (int i = tid; i < B_ * KBANK; i += 256) {
        int b = i >> 6, k = i & 63;
        float s = 0.f;
#pragma unroll
        for (int t = 0; t < T_; t++) s += tf[(b * T_ + t) * KBANK + k];
        sc[i] = s * (1.0f / (float)T_);
    }
    __syncthreads();
    size_t p = (size_t)blockIdx.x * 256 + tid;
    float acc[B_];
#pragma unroll
    for (int b = 0; b < B_; b++) acc[b] = 0.f;
    for (int k = 0; k < KBANK; k++) {
        float wv = W[(size_t)k * PPW + p];
#pragma unroll
        for (int b = 0; b < B_; b++) acc[b] = fmaf(sc[b * KBANK + k], wv, acc[b]);
    }
#pragma unroll
    for (int b = 0; b < B_; b++) g_lp[(size_t)b * PPW + p] = acc[b];
}

// ---------------------------------------------------------------------------
// K2: pack A fragments — smem transpose, fully parallel.
// grid (oq*8+kb = 64, b = 16) = 1024 blocks, 256 thr, no serial loop.
// Stage [16 o][16 c][25 tap] slab (coalesced 400-float rows), emit 800 uint4.
// Frag mapping (verified R11): lane=(g*4+t), o0=oq*16+g, c0=2(kb*8+t):
//   x=(o0,c0|c0+1) y=(o0+8,·) z=(o0,c0+8|c0+9) w=(o0+8,·)
// ---------------------------------------------------------------------------
#define APITCH 401   // odd pitch
__global__ __launch_bounds__(256) void apack_kernel() {
    __shared__ float s[16 * APITCH];   // 25.7 KB
    const int oq = blockIdx.x >> 3, kb = blockIdx.x & 7, b = blockIdx.y;
    const int tid = threadIdx.x;
    const float* lpb = g_lp + (size_t)b * PPW + (size_t)(oq * 16) * CIN * 25
                     + (size_t)kb * 400;
    uint4* dstb = g_Af + (size_t)b * 25 * 2048 + oq * 256 + kb * 32;

    // stage slab: 16 o-rows x 400 consecutive floats
#pragma unroll
    for (int i = 0; i < 25; i++) {
        int idx = tid + (i << 8);                  // < 6400
        int o_l = idx / 400, r = idx - o_l * 400;
        s[o_l * APITCH + r] = lpb[(size_t)o_l * CIN * 25 + r];
    }
    __syncthreads();

    // emit 25 taps x 32 lanes, coalesced uint4 stores
#pragma unroll
    for (int i = 0; i < 4; i++) {
        int idx = tid + (i << 8);
        if (idx < 800) {
            int lane = idx & 31, tap = idx >> 5;
            int g = lane >> 2, t = lane & 3;
            const float* r0 = s + g * APITCH + (2 * t) * 25 + tap;   // o=g
            const float* r1 = r0 + 8 * APITCH;                       // o=g+8
            __half2 hx = __floats2half2_rn(r0[0],      r0[25]);
            __half2 hy = __floats2half2_rn(r1[0],      r1[25]);
            __half2 hz = __floats2half2_rn(r0[8 * 25], r0[9 * 25]);
            __half2 hw = __floats2half2_rn(r1[8 * 25], r1[9 * 25]);
            uint4 v;
            v.x = *(unsigned*)&hx; v.y = *(unsigned*)&hy;
            v.z = *(unsigned*)&hz; v.w = *(unsigned*)&hw;
            dstb[(size_t)tap * 2048 + lane] = v;
        }
    }
}

// ---------------------------------------------------------------------------
// K3: g_xph[b][cp][hp][wp] = half2(x[b][2cp][h][w], x[b][2cp+1][h][w]), pad 0
// ---------------------------------------------------------------------------
__global__ __launch_bounds__(256) void xpad_kernel(const float* __restrict__ x) {
    const int cp = blockIdx.x, b = blockIdx.y;
    const float* x0 = x + ((size_t)(b * CIN + 2 * cp) * HH) * WW;
    const float* x1 = x0 + HH * WW;
    unsigned* dst = g_xph + ((size_t)(b * 64 + cp) * HP) * WP;
    for (int i = threadIdx.x; i < HP * WP; i += 256) {
        int hp = i / WP, wp = i - hp * WP;
        int h = hp - 2, w = wp - 2;
        float v0 = 0.f, v1 = 0.f;
        if ((unsigned)h < HH && (unsigned)w < WW) {
            v0 = x0[h * WW + w];
            v1 = x1[h * WW + w];
        }
        __half2 hh = __floats2half2_rn(v0, v1);
        dst[i] = *(unsigned*)&hh;
    }
}

// ---------------------------------------------------------------------------
// K4: conv (UNCHANGED, at its f32-accum tensor floor): 25 tap-GEMMs,
// mma m16n8k16 fp16/fp32. CTA=(b,1 row), 8 warps 4Mx2N, 32x32 warp tile.
// A via coalesced LDG.128 fragments; B halo smem double-buffered; barriers
// only at 4 chunk boundaries. 3 CTAs/SM.
// ---------------------------------------------------------------------------
#define BP   344
#define BBUF (16 * BP)
#define SMW  (2 * BBUF)                // 44032 B

__device__ __forceinline__ void stage_b(uint32_t sb, const unsigned* Xbase,
                                        int cc, int h0) {
    const uint32_t dbase = sb + (uint32_t)((cc & 1) * BBUF) * 4;
    for (int idx = threadIdx.x; idx < 1360; idx += 256) {
        int cp = idx / 85, rem = idx - cp * 85;
        int r = rem / 17, f = rem - r * 17;
        const unsigned* src = Xbase + (size_t)(cc * 16 + cp) * HP * WP
                                    + (h0 + r) * WP + f * 4;
        CP16(dbase + (uint32_t)(cp * BP + r * WP + f * 4) * 4, src);
    }
}

__global__ __launch_bounds__(256, 3) void conv_kernel(float* __restrict__ out) {
    extern __shared__ uint32_t sm[];
    const uint32_t sb = smem_u32(sm);
    const int tid = threadIdx.x;
    const int lane = tid & 31;
    const int wid = tid >> 5;
    const int g = lane >> 2, t = lane & 3;
    const int wm = wid & 3;
    const int wn = wid >> 2;
    const int w0 = wn * 32;
    const int b = blockIdx.y, h0 = blockIdx.x;

    const uint4* __restrict__ Aw = g_Af + ((size_t)b * 25 + 0) * 2048
                                 + (size_t)(wm * 2) * 256 + lane;
    const unsigned* Xbase = g_xph + (size_t)b * 64 * HP * WP;

    float acc[2][4][4];
#pragma unroll
    for (int mt = 0; mt < 2; mt++)
#pragma unroll
        for (int nt = 0; nt < 4; nt++)
#pragma unroll
            for (int q = 0; q < 4; q++) acc[mt][nt][q] = 0.f;

    stage_b(sb, Xbase, 0, h0);
    CP_COMMIT();

#pragma unroll 1
    for (int cc = 0; cc < 4; cc++) {
        CP_WAIT0();
        __syncthreads();
        const uint32_t* sB = sm + (cc & 1) * BBUF;

#pragma unroll 5
        for (int tap = 0; tap < 25; tap++) {
            if (tap == 12 && cc < 3) { stage_b(sb, Xbase, cc + 1, h0); CP_COMMIT(); }
            const int di = tap / 5, dj = tap % 5;
            const uint4* ap = Aw + (size_t)tap * 2048 + cc * 64;
            uint4 a00 = ap[0];
            uint4 a01 = ap[32];
            uint4 a10 = ap[256];
            uint4 a11 = ap[256 + 32];
            const int pixbase = di * WP + dj + w0 + g;
#pragma unroll
            for (int kk = 0; kk < 2; kk++) {
                const uint32_t* bp0 = sB + (kk * 8 + t) * BP + pixbase;
                const uint32_t* bp1 = bp0 + 4 * BP;
                uint4 a0 = kk ? a01 : a00;
                uint4 a1 = kk ? a11 : a10;
#pragma unroll
                for (int nt = 0; nt < 4; nt++) {
                    uint32_t b0 = bp0[nt * 8], b1 = bp1[nt * 8];
                    MMA16816(acc[0][nt], a0, b0, b1);
                    MMA16816(acc[1][nt], a1, b0, b1);
                }
            }
        }
    }

    // ---- epilogue ----
#pragma unroll
    for (int mt = 0; mt < 2; mt++) {
#pragma unroll
        for (int rr = 0; rr < 2; rr++) {
            int cout = wm * 32 + mt * 16 + g + rr * 8;
            float* op = out + (((size_t)b * COUT + cout) * HH + h0) * WW + w0;
#pragma unroll
            for (int nt = 0; nt < 4; nt++) {
                float2 v = make_float2(acc[mt][nt][rr * 2], acc[mt][nt][rr * 2 + 1]);
                *(float2*)(op + nt * 8 + 2 * t) = v;
            }
        }
    }
}

// ---------------------------------------------------------------------------
extern "C" void kernel_launch(void* const* d_in, const int* in_sizes, int n_in,
                              void* d_out, int out_size) {
    (void)in_sizes; (void)n_in; (void)out_size;
    const float* x  = (const float*)d_in[0];   // (16,128,64,64)
    const float* tf = (const float*)d_in[1];   // (16,8,64)
    const float* W  = (const float*)d_in[2];   // (64,128,128,5,5)
    float* out = (float*)d_out;                // (16,128,64,64)

    cudaFuncSetAttribute(conv_kernel, cudaFuncAttributeMaxDynamicSharedMemorySize,
                         SMW * 4);

    lp_kernel<<<PPW / 256, 256>>>(W, tf);
    apack_kernel<<<dim3(64, B_), 256>>>();
    xpad_kernel<<<dim3(64, B_), 256>>>(x);
    conv_kernel<<<dim3(HH, B_), 256, SMW * 4>>>(out);
}